// round 12
// baseline (speedup 1.0000x reference)
#include <cuda_runtime.h>
#include <cstddef>

// ---------------------------------------------------------------------------
// Decoder_73495480369571: 6-layer dense 3D transposed-conv decoder, fp32.
// conv_transpose (transpose_kernel=False, SAME, k=3):
//   stride 1: SAME cross-correlation pad 1.
//   stride 2: per dim: out[2m] = in[m-1]*w[0] + in[m]*w[2]; out[2m+1] = in[m]*w[1]
// Weights DHWIO: w[kz][ky][kx][ci][co] (co contiguous). Acts NCDHW (N=1).
//
// R11: all conv kernels at 128-thread blocks with __launch_bounds__(128,4)
// (L3 restructured from 32-thr to 32co x 4zy blocks); split-K trimmed to one
// full wave (512 blocks) per layer -> halved partial-slab traffic.
// ---------------------------------------------------------------------------

typedef unsigned long long u64;

__device__ __forceinline__ u64 fma2(u64 a, u64 b, u64 c) {
    u64 d;
    asm("fma.rn.f32x2 %0, %1, %2, %3;" : "=l"(d) : "l"(a), "l"(b), "l"(c));
    return d;
}
__device__ __forceinline__ u64 bcast2(float x) {
    u64 d;
    asm("mov.b64 %0, {%1, %2};" : "=l"(d) : "f"(x), "f"(x));
    return d;
}
__device__ __forceinline__ void unpk(u64 v, float& lo, float& hi) {
    asm("mov.b64 {%0, %1}, %2;" : "=f"(lo), "=f"(hi) : "l"(v));
}

template <int PAIRS>
__device__ __forceinline__ void ldwp(const float* __restrict__ p, u64* v) {
    if constexpr (PAIRS == 2) {
        ulonglong2 t = __ldg((const ulonglong2*)p);
        v[0] = t.x; v[1] = t.y;
    } else {
        v[0] = __ldg((const u64*)p);
    }
}

// Scratch (__device__ globals; allocation-free rule).
__device__ float g_h1[512 * 512];
__device__ float g_h2[256 * 512];
__device__ float g_h3[128 * 4096];
__device__ float g_h4[64 * 4096];
__device__ float g_h5[32 * 32768];
__device__ float g_p1[16 * 512 * 512];
__device__ float g_p2[32 * 256 * 512];
__device__ float g_p3[16 * 128 * 4096];
__device__ float g_p4[16 * 64 * 4096];
__device__ float g_p5[4  * 32 * 32768];

// ---------------------------------------------------------------------------
// Stride-1 SAME conv, y-PAIRED, 4 consecutive co per thread.
// ---------------------------------------------------------------------------
template <int DX, int XTB, int YP>
__global__ void __launch_bounds__(128, 4)
ct_s1y(const float* __restrict__ in, const float* __restrict__ w,
       float* __restrict__ out, int Ci, int Co, int ciChunk, int splitBase)
{
    constexpr int XW = 8;
    constexpr int YPG = (DX / 2) / YP;
    const int split = blockIdx.z + splitBase;
    const int co = threadIdx.x * 4;
    const int x0 = (XTB > 1) ? (int)threadIdx.y * XW : 0;
    const int yp = (XTB > 1) ? (int)threadIdx.z : (int)threadIdx.y;
    const int z  = blockIdx.x / YPG;
    const int y0 = ((blockIdx.x % YPG) * YP + yp) * 2;
    const int ci0 = split * ciChunk;
    out += (size_t)split * Co * (DX * DX * DX);

    u64 acc[2][2][XW];   // [yout][pair][x]
#pragma unroll
    for (int a = 0; a < 2; a++)
#pragma unroll
        for (int p = 0; p < 2; p++)
#pragma unroll
            for (int j = 0; j < XW; j++) acc[a][p][j] = 0ull;

    const int CC = Ci * Co;
    for (int ci = ci0; ci < ci0 + ciChunk; ci++) {
        const float* inc = in + (size_t)ci * (DX * DX * DX);
#pragma unroll
        for (int kz = 0; kz < 3; kz++) {
            const int zi = z + kz - 1;
            if (zi < 0 || zi >= DX) continue;
            const float* wb = w + (size_t)(kz * 9) * CC + (size_t)ci * Co + co;
            const float* plane = inc + zi * DX * DX;
            u64 wbuf[2][3][2];   // [r&1][kx][pair]
#pragma unroll
            for (int r = 0; r < 4; r++) {          // rows y0-1 .. y0+2
                if (r <= 2) {
#pragma unroll
                    for (int kx = 0; kx < 3; kx++)
                        ldwp<2>(wb + (size_t)(r * 3 + kx) * CC, wbuf[r & 1][kx]);
                }
                const int yi = y0 - 1 + r;
                if (yi >= 0 && yi < DX) {
                    const float* row = plane + yi * DX + x0;
                    float4 t0 = __ldg((const float4*)row);
                    float4 t1 = __ldg((const float4*)(row + 4));
                    u64 rp[XW + 2];                // rp[k] = input x = x0-1+k
                    rp[0] = (x0 > 0) ? bcast2(__ldg(row - 1)) : 0ull;
                    rp[1] = bcast2(t0.x); rp[2] = bcast2(t0.y);
                    rp[3] = bcast2(t0.z); rp[4] = bcast2(t0.w);
                    rp[5] = bcast2(t1.x); rp[6] = bcast2(t1.y);
                    rp[7] = bcast2(t1.z); rp[8] = bcast2(t1.w);
                    rp[9] = (x0 + XW < DX) ? bcast2(__ldg(row + XW)) : 0ull;
                    if (r <= 2) {                  // out y0 uses ky=r
#pragma unroll
                        for (int p = 0; p < 2; p++)
#pragma unroll
                            for (int kx = 0; kx < 3; kx++)
#pragma unroll
                                for (int j = 0; j < XW; j++)
                                    acc[0][p][j] = fma2(rp[j + kx], wbuf[r & 1][kx][p], acc[0][p][j]);
                    }
                    if (r >= 1) {                  // out y0+1 uses ky=r-1
#pragma unroll
                        for (int p = 0; p < 2; p++)
#pragma unroll
                            for (int kx = 0; kx < 3; kx++)
#pragma unroll
                                for (int j = 0; j < XW; j++)
                                    acc[1][p][j] = fma2(rp[j + kx], wbuf[(r - 1) & 1][kx][p], acc[1][p][j]);
                    }
                }
            }
        }
    }

#pragma unroll
    for (int yo = 0; yo < 2; yo++)
#pragma unroll
        for (int p = 0; p < 2; p++) {
            float lo[XW], hi[XW];
#pragma unroll
            for (int j = 0; j < XW; j++) unpk(acc[yo][p][j], lo[j], hi[j]);
            float* bLo = out + (((size_t)(co + 2 * p) * DX + z) * DX + (y0 + yo)) * DX + x0;
            float* bHi = bLo + (size_t)DX * DX * DX;
            ((float4*)bLo)[0] = make_float4(lo[0], lo[1], lo[2], lo[3]);
            ((float4*)bLo)[1] = make_float4(lo[4], lo[5], lo[6], lo[7]);
            ((float4*)bHi)[0] = make_float4(hi[0], hi[1], hi[2], hi[3]);
            ((float4*)bHi)[1] = make_float4(hi[4], hi[5], hi[6], hi[7]);
        }
}

// ---------------------------------------------------------------------------
// Stride-2 transposed conv, packed co-pairs, (co, zy)-threaded blocks.
// blockDim (CO_T, ZYT); zy = blockIdx.x * ZYT + threadIdx.y.
// ---------------------------------------------------------------------------
template <int DXIN, int PAIRS, int ZYT>
__global__ void __launch_bounds__(128, 4)
ct_s2p(const float* __restrict__ in, const float* __restrict__ w,
       float* __restrict__ out, int Ci, int Co, int ciChunk)
{
    constexpr int DO = 2 * DXIN;
    const int co = threadIdx.x * (2 * PAIRS);
    const int zy = blockIdx.x * ZYT + threadIdx.y;
    const int z  = zy / DO;
    const int y  = zy % DO;
    const int ci0 = blockIdx.z * ciChunk;
    out += (size_t)blockIdx.z * Co * (DO * DO * DO);

    u64 acc[PAIRS][DO];
#pragma unroll
    for (int p = 0; p < PAIRS; p++)
#pragma unroll
        for (int i = 0; i < DO; i++) acc[p][i] = 0ull;

    int zk[2], zi[2], nz = 0;
#pragma unroll
    for (int k = 0; k < 3; k++)
        if (((z + k) & 1) == 0) {
            int t = (z + k - 2) / 2;
            if (t >= 0 && t < DXIN) { zk[nz] = k; zi[nz] = t; nz++; }
        }
    int yk[2], yi[2], ny = 0;
#pragma unroll
    for (int k = 0; k < 3; k++)
        if (((y + k) & 1) == 0) {
            int t = (y + k - 2) / 2;
            if (t >= 0 && t < DXIN) { yk[ny] = k; yi[ny] = t; ny++; }
        }

    const int CC = Ci * Co;
#pragma unroll 2
    for (int ci = ci0; ci < ci0 + ciChunk; ci++) {
        const float* inc = in + (size_t)ci * (DXIN * DXIN * DXIN);
        for (int a = 0; a < nz; a++) {
            for (int b = 0; b < ny; b++) {
                const float* row = inc + (zi[a] * DXIN + yi[b]) * DXIN;
                u64 rp[DXIN];
#pragma unroll
                for (int q = 0; q < DXIN / 4; q++) {
                    float4 t = __ldg((const float4*)row + q);
                    rp[4 * q + 0] = bcast2(t.x); rp[4 * q + 1] = bcast2(t.y);
                    rp[4 * q + 2] = bcast2(t.z); rp[4 * q + 3] = bcast2(t.w);
                }
                const float* wp = w + (size_t)((zk[a] * 3 + yk[b]) * 3) * CC
                                    + (size_t)ci * Co + co;
                u64 w0[PAIRS], w1[PAIRS], w2[PAIRS];
                ldwp<PAIRS>(wp, w0); ldwp<PAIRS>(wp + CC, w1); ldwp<PAIRS>(wp + 2 * CC, w2);
#pragma unroll
                for (int p = 0; p < PAIRS; p++) {
#pragma unroll
                    for (int m = 1; m < DXIN; m++) acc[p][2 * m]     = fma2(rp[m - 1], w0[p], acc[p][2 * m]);
#pragma unroll
                    for (int m = 0; m < DXIN; m++) acc[p][2 * m + 1] = fma2(rp[m],     w1[p], acc[p][2 * m + 1]);
#pragma unroll
                    for (int m = 0; m < DXIN; m++) acc[p][2 * m]     = fma2(rp[m],     w2[p], acc[p][2 * m]);
                }
            }
        }
    }

#pragma unroll
    for (int p = 0; p < PAIRS; p++) {
        float lo[DO], hi[DO];
#pragma unroll
        for (int xo = 0; xo < DO; xo++) unpk(acc[p][xo], lo[xo], hi[xo]);
        float* opLo = out + (((size_t)(co + 2 * p) * DO + z) * DO + y) * DO;
        float* opHi = opLo + (size_t)DO * DO * DO;
#pragma unroll
        for (int xo = 0; xo < DO; xo++) { opLo[xo] = lo[xo]; opHi[xo] = hi[xo]; }
    }
}

// ---------------------------------------------------------------------------
// Stride-2 packed, (z,y)-tiled blocks (L5).
// ---------------------------------------------------------------------------
template <int DXIN, int ZYT>
__global__ void __launch_bounds__(128, 4)
ct_s2pz(const float* __restrict__ in, const float* __restrict__ w,
        float* __restrict__ out, int Ci, int Co, int ciChunk)
{
    constexpr int DO = 2 * DXIN;
    const int co = threadIdx.x * 2;
    const int zy = blockIdx.x * ZYT + threadIdx.y;
    const int z  = zy / DO;
    const int y  = zy % DO;
    const int ci0 = blockIdx.z * ciChunk;
    out += (size_t)blockIdx.z * Co * (DO * DO * DO);

    u64 acc[DO];
#pragma unroll
    for (int i = 0; i < DO; i++) acc[i] = 0ull;

    int zk[2], zi[2], nz = 0;
#pragma unroll
    for (int k = 0; k < 3; k++)
        if (((z + k) & 1) == 0) {
            int t = (z + k - 2) / 2;
            if (t >= 0 && t < DXIN) { zk[nz] = k; zi[nz] = t; nz++; }
        }
    int yk[2], yi[2], ny = 0;
#pragma unroll
    for (int k = 0; k < 3; k++)
        if (((y + k) & 1) == 0) {
            int t = (y + k - 2) / 2;
            if (t >= 0 && t < DXIN) { yk[ny] = k; yi[ny] = t; ny++; }
        }

    const int CC = Ci * Co;
#pragma unroll 2
    for (int ci = ci0; ci < ci0 + ciChunk; ci++) {
        const float* inc = in + (size_t)ci * (DXIN * DXIN * DXIN);
        for (int a = 0; a < nz; a++) {
            for (int b = 0; b < ny; b++) {
                const float* row = inc + (zi[a] * DXIN + yi[b]) * DXIN;
                u64 rp[DXIN];
#pragma unroll
                for (int q = 0; q < DXIN / 4; q++) {
                    float4 t = __ldg((const float4*)row + q);
                    rp[4 * q + 0] = bcast2(t.x); rp[4 * q + 1] = bcast2(t.y);
                    rp[4 * q + 2] = bcast2(t.z); rp[4 * q + 3] = bcast2(t.w);
                }
                const float* wp = w + (size_t)((zk[a] * 3 + yk[b]) * 3) * CC
                                    + (size_t)ci * Co + co;
                u64 w0, w1, w2;
                ldwp<1>(wp, &w0); ldwp<1>(wp + CC, &w1); ldwp<1>(wp + 2 * CC, &w2);
#pragma unroll
                for (int m = 1; m < DXIN; m++) acc[2 * m]     = fma2(rp[m - 1], w0, acc[2 * m]);
#pragma unroll
                for (int m = 0; m < DXIN; m++) acc[2 * m + 1] = fma2(rp[m],     w1, acc[2 * m + 1]);
#pragma unroll
                for (int m = 0; m < DXIN; m++) acc[2 * m]     = fma2(rp[m],     w2, acc[2 * m]);
            }
        }
    }

    float lo[DO], hi[DO];
#pragma unroll
    for (int xo = 0; xo < DO; xo++) unpk(acc[xo], lo[xo], hi[xo]);
    float* opLo = out + (((size_t)co * DO + z) * DO + y) * DO;
    float* opHi = opLo + (size_t)DO * DO * DO;
#pragma unroll
    for (int q = 0; q < DO / 4; q++) {
        ((float4*)opLo)[q] = make_float4(lo[4*q], lo[4*q+1], lo[4*q+2], lo[4*q+3]);
        ((float4*)opHi)[q] = make_float4(hi[4*q], hi[4*q+1], hi[4*q+2], hi[4*q+3]);
    }
}

// ---------------------------------------------------------------------------
// Final layer: Ci=32 -> Co=1, D=32, stride 1, no ReLU.
// ---------------------------------------------------------------------------
__global__ void ct_final(const float* __restrict__ in, const float* __restrict__ w,
                         float* __restrict__ out)
{
    constexpr int Ci = 32, D = 32;
    __shared__ float ws[27 * Ci];
    for (int i = threadIdx.x; i < 27 * Ci; i += blockDim.x) ws[i] = w[i];
    __syncthreads();

    const int idx = blockIdx.x * blockDim.x + threadIdx.x;
    const int x = idx & 31;
    const int y = (idx >> 5) & 31;
    const int z = idx >> 10;

    float acc = 0.f;
#pragma unroll
    for (int kz = 0; kz < 3; kz++) {
        const int zi = z + kz - 1;
        if (zi < 0 || zi >= D) continue;
#pragma unroll
        for (int ky = 0; ky < 3; ky++) {
            const int yi = y + ky - 1;
            if (yi < 0 || yi >= D) continue;
#pragma unroll
            for (int kx = 0; kx < 3; kx++) {
                const int xi = x + kx - 1;
                if (xi < 0 || xi >= D) continue;
                const float* ip = in + (zi * D + yi) * D + xi;
                const float* wk = ws + ((kz * 3 + ky) * 3 + kx) * Ci;
#pragma unroll 8
                for (int ci = 0; ci < Ci; ci++)
                    acc += __ldg(ip + (size_t)ci * D * D * D) * wk[ci];
            }
        }
    }
    out[idx] = acc;
}

// Split-K reduction + ReLU, 8-way ILP, fixed order (deterministic).
__global__ void reduce_relu4(const float4* __restrict__ part, float4* __restrict__ out,
                             int n4, int S)
{
    const int i = blockIdx.x * blockDim.x + threadIdx.x;
    if (i >= n4) return;
    float4 a[8];
#pragma unroll
    for (int k = 0; k < 8; k++) a[k] = make_float4(0.f, 0.f, 0.f, 0.f);
    int s = 0;
    for (; s + 8 <= S; s += 8) {
#pragma unroll
        for (int k = 0; k < 8; k++) {
            float4 p = part[(size_t)(s + k) * n4 + i];
            a[k].x += p.x; a[k].y += p.y; a[k].z += p.z; a[k].w += p.w;
        }
    }
    for (; s < S; s++) {
        float4 p = part[(size_t)s * n4 + i];
        a[0].x += p.x; a[0].y += p.y; a[0].z += p.z; a[0].w += p.w;
    }
    float4 v;
    v.x = ((a[0].x + a[1].x) + (a[2].x + a[3].x)) + ((a[4].x + a[5].x) + (a[6].x + a[7].x));
    v.y = ((a[0].y + a[1].y) + (a[2].y + a[3].y)) + ((a[4].y + a[5].y) + (a[6].y + a[7].y));
    v.z = ((a[0].z + a[1].z) + (a[2].z + a[3].z)) + ((a[4].z + a[5].z) + (a[6].z + a[7].z));
    v.w = ((a[0].w + a[1].w) + (a[2].w + a[3].w)) + ((a[4].w + a[5].w) + (a[6].w + a[7].w));
    v.x = fmaxf(v.x, 0.f); v.y = fmaxf(v.y, 0.f);
    v.z = fmaxf(v.z, 0.f); v.w = fmaxf(v.w, 0.f);
    out[i] = v;
}

// ---------------------------------------------------------------------------
extern "C" void kernel_launch(void* const* d_in, const int* in_sizes, int n_in,
                              void* d_out, int out_size)
{
    (void)in_sizes; (void)n_in; (void)out_size;
    const float* x  = (const float*)d_in[0];
    const float* w1 = (const float*)d_in[1];
    const float* w2 = (const float*)d_in[2];
    const float* w3 = (const float*)d_in[3];
    const float* w4 = (const float*)d_in[4];
    const float* w5 = (const float*)d_in[5];
    const float* w6 = (const float*)d_in[6];
    float* out = (float*)d_out;

    float *h1, *h2, *h3, *h4, *h5, *p1, *p2, *p3, *p4, *p5;
    cudaGetSymbolAddress((void**)&h1, g_h1);
    cudaGetSymbolAddress((void**)&h2, g_h2);
    cudaGetSymbolAddress((void**)&h3, g_h3);
    cudaGetSymbolAddress((void**)&h4, g_h4);
    cudaGetSymbolAddress((void**)&h5, g_h5);
    cudaGetSymbolAddress((void**)&p1, g_p1);
    cudaGetSymbolAddress((void**)&p2, g_p2);
    cudaGetSymbolAddress((void**)&p3, g_p3);
    cudaGetSymbolAddress((void**)&p4, g_p4);
    cudaGetSymbolAddress((void**)&p5, g_p5);

    // L1: 1024->512, 4^3->8^3, s2. 128 co-quad threads, split 16 (1024 blocks).
    ct_s2p<4, 2, 1><<<dim3(64, 1, 16), dim3(128, 1)>>>(x, w1, p1, 1024, 512, 64);
    reduce_relu4<<<(512 * 512 / 4 + 255) / 256, 256>>>((const float4*)p1, (float4*)h1,
                                                       512 * 512 / 4, 16);

    // L2: 512->256, 8^3, s1, y-paired. split 32 (512 blocks, one full wave).
    ct_s1y<8, 1, 2><<<dim3(16, 1, 32), dim3(64, 2, 1)>>>(h1, w2, p2, 512, 256, 16, 0);
    reduce_relu4<<<(256 * 512 / 4 + 255) / 256, 256>>>((const float4*)p2, (float4*)h2,
                                                       256 * 512 / 4, 32);

    // L3: 256->128, 8^3->16^3, s2. 32 co-quads x 4 zy = 128 thr, split 16
    // (1024 blocks).
    ct_s2p<8, 2, 4><<<dim3(64, 1, 16), dim3(32, 4)>>>(h2, w3, p3, 256, 128, 16);
    reduce_relu4<<<(128 * 4096 / 4 + 255) / 256, 256>>>((const float4*)p3, (float4*)h3,
                                                        128 * 4096 / 4, 16);

    // L4: 128->64, 16^3, s1, y-paired. split 16 (512 blocks).
    ct_s1y<16, 2, 4><<<dim3(32, 1, 16), dim3(16, 2, 4)>>>(h3, w4, p4, 128, 64, 8, 0);
    reduce_relu4<<<(64 * 4096 / 4 + 255) / 256, 256>>>((const float4*)p4, (float4*)h4,
                                                       64 * 4096 / 4, 16);

    // L5: 64->32, 16^3->32^3, s2 packed. split 4 (512 blocks).
    ct_s2pz<16, 8><<<dim3(128, 1, 4), dim3(16, 8, 1)>>>(h4, w5, p5, 64, 32, 16);
    reduce_relu4<<<(32 * 32768 / 4 + 255) / 256, 256>>>((const float4*)p5, (float4*)h5,
                                                        32 * 32768 / 4, 4);

    // L6: 32->1, 32^3, s1, no ReLU.
    ct_final<<<256, 128>>>(h5, w6, out);
}

// round 13
// speedup vs baseline: 1.0220x; 1.0220x over previous
#include <cuda_runtime.h>
#include <cstddef>

// ---------------------------------------------------------------------------
// Decoder_73495480369571: 6-layer dense 3D transposed-conv decoder, fp32.
// conv_transpose (transpose_kernel=False, SAME, k=3):
//   stride 1: SAME cross-correlation pad 1.
//   stride 2: per dim: out[2m] = in[m-1]*w[0] + in[m]*w[2]; out[2m+1] = in[m]*w[1]
// Weights DHWIO: w[kz][ky][kx][ci][co] (co contiguous). Acts NCDHW (N=1).
//
// R12: revert R11's split-K halving (violated the 4-blocks/SM residency rule
// proven in R10); keep only the L3 128-thread-block restructure and
// __launch_bounds__(128,4) everywhere. Splits: L2 64, L4 32, L5 8 (R10).
// ---------------------------------------------------------------------------

typedef unsigned long long u64;

__device__ __forceinline__ u64 fma2(u64 a, u64 b, u64 c) {
    u64 d;
    asm("fma.rn.f32x2 %0, %1, %2, %3;" : "=l"(d) : "l"(a), "l"(b), "l"(c));
    return d;
}
__device__ __forceinline__ u64 bcast2(float x) {
    u64 d;
    asm("mov.b64 %0, {%1, %2};" : "=l"(d) : "f"(x), "f"(x));
    return d;
}
__device__ __forceinline__ void unpk(u64 v, float& lo, float& hi) {
    asm("mov.b64 {%0, %1}, %2;" : "=f"(lo), "=f"(hi) : "l"(v));
}

template <int PAIRS>
__device__ __forceinline__ void ldwp(const float* __restrict__ p, u64* v) {
    if constexpr (PAIRS == 2) {
        ulonglong2 t = __ldg((const ulonglong2*)p);
        v[0] = t.x; v[1] = t.y;
    } else {
        v[0] = __ldg((const u64*)p);
    }
}

// Scratch (__device__ globals; allocation-free rule).
__device__ float g_h1[512 * 512];
__device__ float g_h2[256 * 512];
__device__ float g_h3[128 * 4096];
__device__ float g_h4[64 * 4096];
__device__ float g_h5[32 * 32768];
__device__ float g_p1[16 * 512 * 512];
__device__ float g_p2[64 * 256 * 512];
__device__ float g_p3[16 * 128 * 4096];
__device__ float g_p4[32 * 64 * 4096];
__device__ float g_p5[8  * 32 * 32768];

// ---------------------------------------------------------------------------
// Stride-1 SAME conv, y-PAIRED, 4 consecutive co per thread (R10 version).
// ---------------------------------------------------------------------------
template <int DX, int XTB, int YP>
__global__ void __launch_bounds__(128, 4)
ct_s1y(const float* __restrict__ in, const float* __restrict__ w,
       float* __restrict__ out, int Ci, int Co, int ciChunk, int splitBase)
{
    constexpr int XW = 8;
    constexpr int YPG = (DX / 2) / YP;
    const int split = blockIdx.z + splitBase;
    const int co = threadIdx.x * 4;
    const int x0 = (XTB > 1) ? (int)threadIdx.y * XW : 0;
    const int yp = (XTB > 1) ? (int)threadIdx.z : (int)threadIdx.y;
    const int z  = blockIdx.x / YPG;
    const int y0 = ((blockIdx.x % YPG) * YP + yp) * 2;
    const int ci0 = split * ciChunk;
    out += (size_t)split * Co * (DX * DX * DX);

    u64 acc[2][2][XW];   // [yout][pair][x]
#pragma unroll
    for (int a = 0; a < 2; a++)
#pragma unroll
        for (int p = 0; p < 2; p++)
#pragma unroll
            for (int j = 0; j < XW; j++) acc[a][p][j] = 0ull;

    const int CC = Ci * Co;
    for (int ci = ci0; ci < ci0 + ciChunk; ci++) {
        const float* inc = in + (size_t)ci * (DX * DX * DX);
#pragma unroll
        for (int kz = 0; kz < 3; kz++) {
            const int zi = z + kz - 1;
            if (zi < 0 || zi >= DX) continue;
            const float* wb = w + (size_t)(kz * 9) * CC + (size_t)ci * Co + co;
            const float* plane = inc + zi * DX * DX;
            u64 wbuf[2][3][2];   // [r&1][kx][pair]
#pragma unroll
            for (int r = 0; r < 4; r++) {          // rows y0-1 .. y0+2
                if (r <= 2) {
#pragma unroll
                    for (int kx = 0; kx < 3; kx++)
                        ldwp<2>(wb + (size_t)(r * 3 + kx) * CC, wbuf[r & 1][kx]);
                }
                const int yi = y0 - 1 + r;
                if (yi >= 0 && yi < DX) {
                    const float* row = plane + yi * DX + x0;
                    float4 t0 = __ldg((const float4*)row);
                    float4 t1 = __ldg((const float4*)(row + 4));
                    u64 rp[XW + 2];                // rp[k] = input x = x0-1+k
                    rp[0] = (x0 > 0) ? bcast2(__ldg(row - 1)) : 0ull;
                    rp[1] = bcast2(t0.x); rp[2] = bcast2(t0.y);
                    rp[3] = bcast2(t0.z); rp[4] = bcast2(t0.w);
                    rp[5] = bcast2(t1.x); rp[6] = bcast2(t1.y);
                    rp[7] = bcast2(t1.z); rp[8] = bcast2(t1.w);
                    rp[9] = (x0 + XW < DX) ? bcast2(__ldg(row + XW)) : 0ull;
                    if (r <= 2) {                  // out y0 uses ky=r
#pragma unroll
                        for (int p = 0; p < 2; p++)
#pragma unroll
                            for (int kx = 0; kx < 3; kx++)
#pragma unroll
                                for (int j = 0; j < XW; j++)
                                    acc[0][p][j] = fma2(rp[j + kx], wbuf[r & 1][kx][p], acc[0][p][j]);
                    }
                    if (r >= 1) {                  // out y0+1 uses ky=r-1
#pragma unroll
                        for (int p = 0; p < 2; p++)
#pragma unroll
                            for (int kx = 0; kx < 3; kx++)
#pragma unroll
                                for (int j = 0; j < XW; j++)
                                    acc[1][p][j] = fma2(rp[j + kx], wbuf[(r - 1) & 1][kx][p], acc[1][p][j]);
                    }
                }
            }
        }
    }

#pragma unroll
    for (int yo = 0; yo < 2; yo++)
#pragma unroll
        for (int p = 0; p < 2; p++) {
            float lo[XW], hi[XW];
#pragma unroll
            for (int j = 0; j < XW; j++) unpk(acc[yo][p][j], lo[j], hi[j]);
            float* bLo = out + (((size_t)(co + 2 * p) * DX + z) * DX + (y0 + yo)) * DX + x0;
            float* bHi = bLo + (size_t)DX * DX * DX;
            ((float4*)bLo)[0] = make_float4(lo[0], lo[1], lo[2], lo[3]);
            ((float4*)bLo)[1] = make_float4(lo[4], lo[5], lo[6], lo[7]);
            ((float4*)bHi)[0] = make_float4(hi[0], hi[1], hi[2], hi[3]);
            ((float4*)bHi)[1] = make_float4(hi[4], hi[5], hi[6], hi[7]);
        }
}

// ---------------------------------------------------------------------------
// Stride-2 transposed conv, packed co-pairs, (co, zy)-threaded blocks.
// blockDim (CO_T, ZYT); zy = blockIdx.x * ZYT + threadIdx.y.
// ---------------------------------------------------------------------------
template <int DXIN, int PAIRS, int ZYT>
__global__ void __launch_bounds__(128, 4)
ct_s2p(const float* __restrict__ in, const float* __restrict__ w,
       float* __restrict__ out, int Ci, int Co, int ciChunk)
{
    constexpr int DO = 2 * DXIN;
    const int co = threadIdx.x * (2 * PAIRS);
    const int zy = blockIdx.x * ZYT + threadIdx.y;
    const int z  = zy / DO;
    const int y  = zy % DO;
    const int ci0 = blockIdx.z * ciChunk;
    out += (size_t)blockIdx.z * Co * (DO * DO * DO);

    u64 acc[PAIRS][DO];
#pragma unroll
    for (int p = 0; p < PAIRS; p++)
#pragma unroll
        for (int i = 0; i < DO; i++) acc[p][i] = 0ull;

    int zk[2], zi[2], nz = 0;
#pragma unroll
    for (int k = 0; k < 3; k++)
        if (((z + k) & 1) == 0) {
            int t = (z + k - 2) / 2;
            if (t >= 0 && t < DXIN) { zk[nz] = k; zi[nz] = t; nz++; }
        }
    int yk[2], yi[2], ny = 0;
#pragma unroll
    for (int k = 0; k < 3; k++)
        if (((y + k) & 1) == 0) {
            int t = (y + k - 2) / 2;
            if (t >= 0 && t < DXIN) { yk[ny] = k; yi[ny] = t; ny++; }
        }

    const int CC = Ci * Co;
#pragma unroll 2
    for (int ci = ci0; ci < ci0 + ciChunk; ci++) {
        const float* inc = in + (size_t)ci * (DXIN * DXIN * DXIN);
        for (int a = 0; a < nz; a++) {
            for (int b = 0; b < ny; b++) {
                const float* row = inc + (zi[a] * DXIN + yi[b]) * DXIN;
                u64 rp[DXIN];
#pragma unroll
                for (int q = 0; q < DXIN / 4; q++) {
                    float4 t = __ldg((const float4*)row + q);
                    rp[4 * q + 0] = bcast2(t.x); rp[4 * q + 1] = bcast2(t.y);
                    rp[4 * q + 2] = bcast2(t.z); rp[4 * q + 3] = bcast2(t.w);
                }
                const float* wp = w + (size_t)((zk[a] * 3 + yk[b]) * 3) * CC
                                    + (size_t)ci * Co + co;
                u64 w0[PAIRS], w1[PAIRS], w2[PAIRS];
                ldwp<PAIRS>(wp, w0); ldwp<PAIRS>(wp + CC, w1); ldwp<PAIRS>(wp + 2 * CC, w2);
#pragma unroll
                for (int p = 0; p < PAIRS; p++) {
#pragma unroll
                    for (int m = 1; m < DXIN; m++) acc[p][2 * m]     = fma2(rp[m - 1], w0[p], acc[p][2 * m]);
#pragma unroll
                    for (int m = 0; m < DXIN; m++) acc[p][2 * m + 1] = fma2(rp[m],     w1[p], acc[p][2 * m + 1]);
#pragma unroll
                    for (int m = 0; m < DXIN; m++) acc[p][2 * m]     = fma2(rp[m],     w2[p], acc[p][2 * m]);
                }
            }
        }
    }

#pragma unroll
    for (int p = 0; p < PAIRS; p++) {
        float lo[DO], hi[DO];
#pragma unroll
        for (int xo = 0; xo < DO; xo++) unpk(acc[p][xo], lo[xo], hi[xo]);
        float* opLo = out + (((size_t)(co + 2 * p) * DO + z) * DO + y) * DO;
        float* opHi = opLo + (size_t)DO * DO * DO;
#pragma unroll
        for (int xo = 0; xo < DO; xo++) { opLo[xo] = lo[xo]; opHi[xo] = hi[xo]; }
    }
}

// ---------------------------------------------------------------------------
// Stride-2 packed, (z,y)-tiled blocks (L5).
// ---------------------------------------------------------------------------
template <int DXIN, int ZYT>
__global__ void __launch_bounds__(128, 4)
ct_s2pz(const float* __restrict__ in, const float* __restrict__ w,
        float* __restrict__ out, int Ci, int Co, int ciChunk)
{
    constexpr int DO = 2 * DXIN;
    const int co = threadIdx.x * 2;
    const int zy = blockIdx.x * ZYT + threadIdx.y;
    const int z  = zy / DO;
    const int y  = zy % DO;
    const int ci0 = blockIdx.z * ciChunk;
    out += (size_t)blockIdx.z * Co * (DO * DO * DO);

    u64 acc[DO];
#pragma unroll
    for (int i = 0; i < DO; i++) acc[i] = 0ull;

    int zk[2], zi[2], nz = 0;
#pragma unroll
    for (int k = 0; k < 3; k++)
        if (((z + k) & 1) == 0) {
            int t = (z + k - 2) / 2;
            if (t >= 0 && t < DXIN) { zk[nz] = k; zi[nz] = t; nz++; }
        }
    int yk[2], yi[2], ny = 0;
#pragma unroll
    for (int k = 0; k < 3; k++)
        if (((y + k) & 1) == 0) {
            int t = (y + k - 2) / 2;
            if (t >= 0 && t < DXIN) { yk[ny] = k; yi[ny] = t; ny++; }
        }

    const int CC = Ci * Co;
#pragma unroll 2
    for (int ci = ci0; ci < ci0 + ciChunk; ci++) {
        const float* inc = in + (size_t)ci * (DXIN * DXIN * DXIN);
        for (int a = 0; a < nz; a++) {
            for (int b = 0; b < ny; b++) {
                const float* row = inc + (zi[a] * DXIN + yi[b]) * DXIN;
                u64 rp[DXIN];
#pragma unroll
                for (int q = 0; q < DXIN / 4; q++) {
                    float4 t = __ldg((const float4*)row + q);
                    rp[4 * q + 0] = bcast2(t.x); rp[4 * q + 1] = bcast2(t.y);
                    rp[4 * q + 2] = bcast2(t.z); rp[4 * q + 3] = bcast2(t.w);
                }
                const float* wp = w + (size_t)((zk[a] * 3 + yk[b]) * 3) * CC
                                    + (size_t)ci * Co + co;
                u64 w0, w1, w2;
                ldwp<1>(wp, &w0); ldwp<1>(wp + CC, &w1); ldwp<1>(wp + 2 * CC, &w2);
#pragma unroll
                for (int m = 1; m < DXIN; m++) acc[2 * m]     = fma2(rp[m - 1], w0, acc[2 * m]);
#pragma unroll
                for (int m = 0; m < DXIN; m++) acc[2 * m + 1] = fma2(rp[m],     w1, acc[2 * m + 1]);
#pragma unroll
                for (int m = 0; m < DXIN; m++) acc[2 * m]     = fma2(rp[m],     w2, acc[2 * m]);
            }
        }
    }

    float lo[DO], hi[DO];
#pragma unroll
    for (int xo = 0; xo < DO; xo++) unpk(acc[xo], lo[xo], hi[xo]);
    float* opLo = out + (((size_t)co * DO + z) * DO + y) * DO;
    float* opHi = opLo + (size_t)DO * DO * DO;
#pragma unroll
    for (int q = 0; q < DO / 4; q++) {
        ((float4*)opLo)[q] = make_float4(lo[4*q], lo[4*q+1], lo[4*q+2], lo[4*q+3]);
        ((float4*)opHi)[q] = make_float4(hi[4*q], hi[4*q+1], hi[4*q+2], hi[4*q+3]);
    }
}

// ---------------------------------------------------------------------------
// Final layer: Ci=32 -> Co=1, D=32, stride 1, no ReLU.
// ---------------------------------------------------------------------------
__global__ void ct_final(const float* __restrict__ in, const float* __restrict__ w,
                         float* __restrict__ out)
{
    constexpr int Ci = 32, D = 32;
    __shared__ float ws[27 * Ci];
    for (int i = threadIdx.x; i < 27 * Ci; i += blockDim.x) ws[i] = w[i];
    __syncthreads();

    const int idx = blockIdx.x * blockDim.x + threadIdx.x;
    const int x = idx & 31;
    const int y = (idx >> 5) & 31;
    const int z = idx >> 10;

    float acc = 0.f;
#pragma unroll
    for (int kz = 0; kz < 3; kz++) {
        const int zi = z + kz - 1;
        if (zi < 0 || zi >= D) continue;
#pragma unroll
        for (int ky = 0; ky < 3; ky++) {
            const int yi = y + ky - 1;
            if (yi < 0 || yi >= D) continue;
#pragma unroll
            for (int kx = 0; kx < 3; kx++) {
                const int xi = x + kx - 1;
                if (xi < 0 || xi >= D) continue;
                const float* ip = in + (zi * D + yi) * D + xi;
                const float* wk = ws + ((kz * 3 + ky) * 3 + kx) * Ci;
#pragma unroll 8
                for (int ci = 0; ci < Ci; ci++)
                    acc += __ldg(ip + (size_t)ci * D * D * D) * wk[ci];
            }
        }
    }
    out[idx] = acc;
}

// Split-K reduction + ReLU, 8-way ILP, fixed order (deterministic).
__global__ void reduce_relu4(const float4* __restrict__ part, float4* __restrict__ out,
                             int n4, int S)
{
    const int i = blockIdx.x * blockDim.x + threadIdx.x;
    if (i >= n4) return;
    float4 a[8];
#pragma unroll
    for (int k = 0; k < 8; k++) a[k] = make_float4(0.f, 0.f, 0.f, 0.f);
    int s = 0;
    for (; s + 8 <= S; s += 8) {
#pragma unroll
        for (int k = 0; k < 8; k++) {
            float4 p = part[(size_t)(s + k) * n4 + i];
            a[k].x += p.x; a[k].y += p.y; a[k].z += p.z; a[k].w += p.w;
        }
    }
    for (; s < S; s++) {
        float4 p = part[(size_t)s * n4 + i];
        a[0].x += p.x; a[0].y += p.y; a[0].z += p.z; a[0].w += p.w;
    }
    float4 v;
    v.x = ((a[0].x + a[1].x) + (a[2].x + a[3].x)) + ((a[4].x + a[5].x) + (a[6].x + a[7].x));
    v.y = ((a[0].y + a[1].y) + (a[2].y + a[3].y)) + ((a[4].y + a[5].y) + (a[6].y + a[7].y));
    v.z = ((a[0].z + a[1].z) + (a[2].z + a[3].z)) + ((a[4].z + a[5].z) + (a[6].z + a[7].z));
    v.w = ((a[0].w + a[1].w) + (a[2].w + a[3].w)) + ((a[4].w + a[5].w) + (a[6].w + a[7].w));
    v.x = fmaxf(v.x, 0.f); v.y = fmaxf(v.y, 0.f);
    v.z = fmaxf(v.z, 0.f); v.w = fmaxf(v.w, 0.f);
    out[i] = v;
}

// ---------------------------------------------------------------------------
extern "C" void kernel_launch(void* const* d_in, const int* in_sizes, int n_in,
                              void* d_out, int out_size)
{
    (void)in_sizes; (void)n_in; (void)out_size;
    const float* x  = (const float*)d_in[0];
    const float* w1 = (const float*)d_in[1];
    const float* w2 = (const float*)d_in[2];
    const float* w3 = (const float*)d_in[3];
    const float* w4 = (const float*)d_in[4];
    const float* w5 = (const float*)d_in[5];
    const float* w6 = (const float*)d_in[6];
    float* out = (float*)d_out;

    float *h1, *h2, *h3, *h4, *h5, *p1, *p2, *p3, *p4, *p5;
    cudaGetSymbolAddress((void**)&h1, g_h1);
    cudaGetSymbolAddress((void**)&h2, g_h2);
    cudaGetSymbolAddress((void**)&h3, g_h3);
    cudaGetSymbolAddress((void**)&h4, g_h4);
    cudaGetSymbolAddress((void**)&h5, g_h5);
    cudaGetSymbolAddress((void**)&p1, g_p1);
    cudaGetSymbolAddress((void**)&p2, g_p2);
    cudaGetSymbolAddress((void**)&p3, g_p3);
    cudaGetSymbolAddress((void**)&p4, g_p4);
    cudaGetSymbolAddress((void**)&p5, g_p5);

    // L1: 1024->512, 4^3->8^3, s2. 128 co-quad threads, split 16 (1024 blocks).
    ct_s2p<4, 2, 1><<<dim3(64, 1, 16), dim3(128, 1)>>>(x, w1, p1, 1024, 512, 64);
    reduce_relu4<<<(512 * 512 / 4 + 255) / 256, 256>>>((const float4*)p1, (float4*)h1,
                                                       512 * 512 / 4, 16);

    // L2: 512->256, 8^3, s1, y-paired. split 64 (1024 blocks, R10 config).
    ct_s1y<8, 1, 2><<<dim3(16, 1, 64), dim3(64, 2, 1)>>>(h1, w2, p2, 512, 256, 8, 0);
    reduce_relu4<<<(256 * 512 / 4 + 255) / 256, 256>>>((const float4*)p2, (float4*)h2,
                                                       256 * 512 / 4, 64);

    // L3: 256->128, 8^3->16^3, s2. 32 co-quads x 4 zy = 128 thr, split 16
    // (1024 blocks) — R11's restructure, kept (matches occupancy theory).
    ct_s2p<8, 2, 4><<<dim3(64, 1, 16), dim3(32, 4)>>>(h2, w3, p3, 256, 128, 16);
    reduce_relu4<<<(128 * 4096 / 4 + 255) / 256, 256>>>((const float4*)p3, (float4*)h3,
                                                        128 * 4096 / 4, 16);

    // L4: 128->64, 16^3, s1, y-paired. split 32 (1024 blocks, R10 config).
    ct_s1y<16, 2, 4><<<dim3(32, 1, 32), dim3(16, 2, 4)>>>(h3, w4, p4, 128, 64, 4, 0);
    reduce_relu4<<<(64 * 4096 / 4 + 255) / 256, 256>>>((const float4*)p4, (float4*)h4,
                                                       64 * 4096 / 4, 32);

    // L5: 64->32, 16^3->32^3, s2 packed. split 8 (1024 blocks, R10 config).
    ct_s2pz<16, 8><<<dim3(128, 1, 8), dim3(16, 8, 1)>>>(h4, w5, p5, 64, 32, 8);
    reduce_relu4<<<(32 * 32768 / 4 + 255) / 256, 256>>>((const float4*)p5, (float4*)h5,
                                                        32 * 32768 / 4, 8);

    // L6: 32->1, 32^3, s1, no ReLU.
    ct_final<<<256, 128>>>(h5, w6, out);
}

// round 14
// speedup vs baseline: 1.0938x; 1.0703x over previous
#include <cuda_runtime.h>
#include <cstddef>

// ---------------------------------------------------------------------------
// Decoder_73495480369571: 6-layer dense 3D transposed-conv decoder, fp32.
// conv_transpose (transpose_kernel=False, SAME, k=3):
//   stride 1: SAME cross-correlation pad 1.
//   stride 2: per dim: out[2m] = in[m-1]*w[0] + in[m]*w[2]; out[2m+1] = in[m]*w[1]
// Weights DHWIO: w[kz][ky][kx][ci][co] (co contiguous). Acts NCDHW (N=1).
//
// R13: conv kernels restored EXACTLY to R10 (the 406us local optimum —
// LB(128,4) on the fat s2 kernels caused spills in R12). New: pair-split
// reduce (2 lanes per output element, shuffle-combined) to double reduce
// parallelism, which all profiles showed was latency-starved.
// ---------------------------------------------------------------------------

typedef unsigned long long u64;

__device__ __forceinline__ u64 fma2(u64 a, u64 b, u64 c) {
    u64 d;
    asm("fma.rn.f32x2 %0, %1, %2, %3;" : "=l"(d) : "l"(a), "l"(b), "l"(c));
    return d;
}
__device__ __forceinline__ u64 bcast2(float x) {
    u64 d;
    asm("mov.b64 %0, {%1, %2};" : "=l"(d) : "f"(x), "f"(x));
    return d;
}
__device__ __forceinline__ void unpk(u64 v, float& lo, float& hi) {
    asm("mov.b64 {%0, %1}, %2;" : "=f"(lo), "=f"(hi) : "l"(v));
}

template <int PAIRS>
__device__ __forceinline__ void ldwp(const float* __restrict__ p, u64* v) {
    if constexpr (PAIRS == 2) {
        ulonglong2 t = __ldg((const ulonglong2*)p);
        v[0] = t.x; v[1] = t.y;
    } else {
        v[0] = __ldg((const u64*)p);
    }
}

// Scratch (__device__ globals; allocation-free rule).
__device__ float g_h1[512 * 512];
__device__ float g_h2[256 * 512];
__device__ float g_h3[128 * 4096];
__device__ float g_h4[64 * 4096];
__device__ float g_h5[32 * 32768];
__device__ float g_p1[16 * 512 * 512];
__device__ float g_p2[64 * 256 * 512];
__device__ float g_p3[16 * 128 * 4096];
__device__ float g_p4[32 * 64 * 4096];
__device__ float g_p5[8  * 32 * 32768];

// ---------------------------------------------------------------------------
// Stride-1 SAME conv, y-PAIRED, 4 consecutive co per thread (R10 exact).
// ---------------------------------------------------------------------------
template <int DX, int XTB, int YP>
__global__ void __launch_bounds__(128, 4)
ct_s1y(const float* __restrict__ in, const float* __restrict__ w,
       float* __restrict__ out, int Ci, int Co, int ciChunk, int splitBase)
{
    constexpr int XW = 8;
    constexpr int YPG = (DX / 2) / YP;
    const int split = blockIdx.z + splitBase;
    const int co = threadIdx.x * 4;
    const int x0 = (XTB > 1) ? (int)threadIdx.y * XW : 0;
    const int yp = (XTB > 1) ? (int)threadIdx.z : (int)threadIdx.y;
    const int z  = blockIdx.x / YPG;
    const int y0 = ((blockIdx.x % YPG) * YP + yp) * 2;
    const int ci0 = split * ciChunk;
    out += (size_t)split * Co * (DX * DX * DX);

    u64 acc[2][2][XW];   // [yout][pair][x]
#pragma unroll
    for (int a = 0; a < 2; a++)
#pragma unroll
        for (int p = 0; p < 2; p++)
#pragma unroll
            for (int j = 0; j < XW; j++) acc[a][p][j] = 0ull;

    const int CC = Ci * Co;
    for (int ci = ci0; ci < ci0 + ciChunk; ci++) {
        const float* inc = in + (size_t)ci * (DX * DX * DX);
#pragma unroll
        for (int kz = 0; kz < 3; kz++) {
            const int zi = z + kz - 1;
            if (zi < 0 || zi >= DX) continue;
            const float* wb = w + (size_t)(kz * 9) * CC + (size_t)ci * Co + co;
            const float* plane = inc + zi * DX * DX;
            u64 wbuf[2][3][2];   // [r&1][kx][pair]
#pragma unroll
            for (int r = 0; r < 4; r++) {          // rows y0-1 .. y0+2
                if (r <= 2) {
#pragma unroll
                    for (int kx = 0; kx < 3; kx++)
                        ldwp<2>(wb + (size_t)(r * 3 + kx) * CC, wbuf[r & 1][kx]);
                }
                const int yi = y0 - 1 + r;
                if (yi >= 0 && yi < DX) {
                    const float* row = plane + yi * DX + x0;
                    float4 t0 = __ldg((const float4*)row);
                    float4 t1 = __ldg((const float4*)(row + 4));
                    u64 rp[XW + 2];                // rp[k] = input x = x0-1+k
                    rp[0] = (x0 > 0) ? bcast2(__ldg(row - 1)) : 0ull;
                    rp[1] = bcast2(t0.x); rp[2] = bcast2(t0.y);
                    rp[3] = bcast2(t0.z); rp[4] = bcast2(t0.w);
                    rp[5] = bcast2(t1.x); rp[6] = bcast2(t1.y);
                    rp[7] = bcast2(t1.z); rp[8] = bcast2(t1.w);
                    rp[9] = (x0 + XW < DX) ? bcast2(__ldg(row + XW)) : 0ull;
                    if (r <= 2) {                  // out y0 uses ky=r
#pragma unroll
                        for (int p = 0; p < 2; p++)
#pragma unroll
                            for (int kx = 0; kx < 3; kx++)
#pragma unroll
                                for (int j = 0; j < XW; j++)
                                    acc[0][p][j] = fma2(rp[j + kx], wbuf[r & 1][kx][p], acc[0][p][j]);
                    }
                    if (r >= 1) {                  // out y0+1 uses ky=r-1
#pragma unroll
                        for (int p = 0; p < 2; p++)
#pragma unroll
                            for (int kx = 0; kx < 3; kx++)
#pragma unroll
                                for (int j = 0; j < XW; j++)
                                    acc[1][p][j] = fma2(rp[j + kx], wbuf[(r - 1) & 1][kx][p], acc[1][p][j]);
                    }
                }
            }
        }
    }

#pragma unroll
    for (int yo = 0; yo < 2; yo++)
#pragma unroll
        for (int p = 0; p < 2; p++) {
            float lo[XW], hi[XW];
#pragma unroll
            for (int j = 0; j < XW; j++) unpk(acc[yo][p][j], lo[j], hi[j]);
            float* bLo = out + (((size_t)(co + 2 * p) * DX + z) * DX + (y0 + yo)) * DX + x0;
            float* bHi = bLo + (size_t)DX * DX * DX;
            ((float4*)bLo)[0] = make_float4(lo[0], lo[1], lo[2], lo[3]);
            ((float4*)bLo)[1] = make_float4(lo[4], lo[5], lo[6], lo[7]);
            ((float4*)bHi)[0] = make_float4(hi[0], hi[1], hi[2], hi[3]);
            ((float4*)bHi)[1] = make_float4(hi[4], hi[5], hi[6], hi[7]);
        }
}

// ---------------------------------------------------------------------------
// Stride-2 transposed conv, packed co-pairs (R10 exact — no launch_bounds).
// ---------------------------------------------------------------------------
template <int DXIN, int PAIRS>
__global__ void ct_s2p(const float* __restrict__ in, const float* __restrict__ w,
                       float* __restrict__ out, int Ci, int Co, int ciChunk)
{
    constexpr int DO = 2 * DXIN;
    const int co = (blockIdx.y * blockDim.x + threadIdx.x) * (2 * PAIRS);
    const int z  = blockIdx.x / DO;
    const int y  = blockIdx.x % DO;
    const int ci0 = blockIdx.z * ciChunk;
    out += (size_t)blockIdx.z * Co * (DO * DO * DO);

    u64 acc[PAIRS][DO];
#pragma unroll
    for (int p = 0; p < PAIRS; p++)
#pragma unroll
        for (int i = 0; i < DO; i++) acc[p][i] = 0ull;

    int zk[2], zi[2], nz = 0;
#pragma unroll
    for (int k = 0; k < 3; k++)
        if (((z + k) & 1) == 0) {
            int t = (z + k - 2) / 2;
            if (t >= 0 && t < DXIN) { zk[nz] = k; zi[nz] = t; nz++; }
        }
    int yk[2], yi[2], ny = 0;
#pragma unroll
    for (int k = 0; k < 3; k++)
        if (((y + k) & 1) == 0) {
            int t = (y + k - 2) / 2;
            if (t >= 0 && t < DXIN) { yk[ny] = k; yi[ny] = t; ny++; }
        }

    const int CC = Ci * Co;
#pragma unroll 2
    for (int ci = ci0; ci < ci0 + ciChunk; ci++) {
        const float* inc = in + (size_t)ci * (DXIN * DXIN * DXIN);
        for (int a = 0; a < nz; a++) {
            for (int b = 0; b < ny; b++) {
                const float* row = inc + (zi[a] * DXIN + yi[b]) * DXIN;
                u64 rp[DXIN];
#pragma unroll
                for (int q = 0; q < DXIN / 4; q++) {
                    float4 t = __ldg((const float4*)row + q);
                    rp[4 * q + 0] = bcast2(t.x); rp[4 * q + 1] = bcast2(t.y);
                    rp[4 * q + 2] = bcast2(t.z); rp[4 * q + 3] = bcast2(t.w);
                }
                const float* wp = w + (size_t)((zk[a] * 3 + yk[b]) * 3) * CC
                                    + (size_t)ci * Co + co;
                u64 w0[PAIRS], w1[PAIRS], w2[PAIRS];
                ldwp<PAIRS>(wp, w0); ldwp<PAIRS>(wp + CC, w1); ldwp<PAIRS>(wp + 2 * CC, w2);
#pragma unroll
                for (int p = 0; p < PAIRS; p++) {
#pragma unroll
                    for (int m = 1; m < DXIN; m++) acc[p][2 * m]     = fma2(rp[m - 1], w0[p], acc[p][2 * m]);
#pragma unroll
                    for (int m = 0; m < DXIN; m++) acc[p][2 * m + 1] = fma2(rp[m],     w1[p], acc[p][2 * m + 1]);
#pragma unroll
                    for (int m = 0; m < DXIN; m++) acc[p][2 * m]     = fma2(rp[m],     w2[p], acc[p][2 * m]);
                }
            }
        }
    }

#pragma unroll
    for (int p = 0; p < PAIRS; p++) {
        float lo[DO], hi[DO];
#pragma unroll
        for (int xo = 0; xo < DO; xo++) unpk(acc[p][xo], lo[xo], hi[xo]);
        float* opLo = out + (((size_t)(co + 2 * p) * DO + z) * DO + y) * DO;
        float* opHi = opLo + (size_t)DO * DO * DO;
#pragma unroll
        for (int xo = 0; xo < DO; xo++) { opLo[xo] = lo[xo]; opHi[xo] = hi[xo]; }
    }
}

// ---------------------------------------------------------------------------
// Stride-2 packed, (z,y)-tiled blocks (L5; R10 exact — no launch_bounds).
// ---------------------------------------------------------------------------
template <int DXIN, int ZYT>
__global__ void ct_s2pz(const float* __restrict__ in, const float* __restrict__ w,
                        float* __restrict__ out, int Ci, int Co, int ciChunk)
{
    constexpr int DO = 2 * DXIN;
    const int co = threadIdx.x * 2;
    const int zy = blockIdx.x * ZYT + threadIdx.y;
    const int z  = zy / DO;
    const int y  = zy % DO;
    const int ci0 = blockIdx.z * ciChunk;
    out += (size_t)blockIdx.z * Co * (DO * DO * DO);

    u64 acc[DO];
#pragma unroll
    for (int i = 0; i < DO; i++) acc[i] = 0ull;

    int zk[2], zi[2], nz = 0;
#pragma unroll
    for (int k = 0; k < 3; k++)
        if (((z + k) & 1) == 0) {
            int t = (z + k - 2) / 2;
            if (t >= 0 && t < DXIN) { zk[nz] = k; zi[nz] = t; nz++; }
        }
    int yk[2], yi[2], ny = 0;
#pragma unroll
    for (int k = 0; k < 3; k++)
        if (((y + k) & 1) == 0) {
            int t = (y + k - 2) / 2;
            if (t >= 0 && t < DXIN) { yk[ny] = k; yi[ny] = t; ny++; }
        }

    const int CC = Ci * Co;
#pragma unroll 2
    for (int ci = ci0; ci < ci0 + ciChunk; ci++) {
        const float* inc = in + (size_t)ci * (DXIN * DXIN * DXIN);
        for (int a = 0; a < nz; a++) {
            for (int b = 0; b < ny; b++) {
                const float* row = inc + (zi[a] * DXIN + yi[b]) * DXIN;
                u64 rp[DXIN];
#pragma unroll
                for (int q = 0; q < DXIN / 4; q++) {
                    float4 t = __ldg((const float4*)row + q);
                    rp[4 * q + 0] = bcast2(t.x); rp[4 * q + 1] = bcast2(t.y);
                    rp[4 * q + 2] = bcast2(t.z); rp[4 * q + 3] = bcast2(t.w);
                }
                const float* wp = w + (size_t)((zk[a] * 3 + yk[b]) * 3) * CC
                                    + (size_t)ci * Co + co;
                u64 w0, w1, w2;
                ldwp<1>(wp, &w0); ldwp<1>(wp + CC, &w1); ldwp<1>(wp + 2 * CC, &w2);
#pragma unroll
                for (int m = 1; m < DXIN; m++) acc[2 * m]     = fma2(rp[m - 1], w0, acc[2 * m]);
#pragma unroll
                for (int m = 0; m < DXIN; m++) acc[2 * m + 1] = fma2(rp[m],     w1, acc[2 * m + 1]);
#pragma unroll
                for (int m = 0; m < DXIN; m++) acc[2 * m]     = fma2(rp[m],     w2, acc[2 * m]);
            }
        }
    }

    float lo[DO], hi[DO];
#pragma unroll
    for (int xo = 0; xo < DO; xo++) unpk(acc[xo], lo[xo], hi[xo]);
    float* opLo = out + (((size_t)co * DO + z) * DO + y) * DO;
    float* opHi = opLo + (size_t)DO * DO * DO;
#pragma unroll
    for (int q = 0; q < DO / 4; q++) {
        ((float4*)opLo)[q] = make_float4(lo[4*q], lo[4*q+1], lo[4*q+2], lo[4*q+3]);
        ((float4*)opHi)[q] = make_float4(hi[4*q], hi[4*q+1], hi[4*q+2], hi[4*q+3]);
    }
}

// ---------------------------------------------------------------------------
// Final layer: Ci=32 -> Co=1, D=32, stride 1, no ReLU.
// ---------------------------------------------------------------------------
__global__ void ct_final(const float* __restrict__ in, const float* __restrict__ w,
                         float* __restrict__ out)
{
    constexpr int Ci = 32, D = 32;
    __shared__ float ws[27 * Ci];
    for (int i = threadIdx.x; i < 27 * Ci; i += blockDim.x) ws[i] = w[i];
    __syncthreads();

    const int idx = blockIdx.x * blockDim.x + threadIdx.x;
    const int x = idx & 31;
    const int y = (idx >> 5) & 31;
    const int z = idx >> 10;

    float acc = 0.f;
#pragma unroll
    for (int kz = 0; kz < 3; kz++) {
        const int zi = z + kz - 1;
        if (zi < 0 || zi >= D) continue;
#pragma unroll
        for (int ky = 0; ky < 3; ky++) {
            const int yi = y + ky - 1;
            if (yi < 0 || yi >= D) continue;
#pragma unroll
            for (int kx = 0; kx < 3; kx++) {
                const int xi = x + kx - 1;
                if (xi < 0 || xi >= D) continue;
                const float* ip = in + (zi * D + yi) * D + xi;
                const float* wk = ws + ((kz * 3 + ky) * 3 + kx) * Ci;
#pragma unroll 8
                for (int ci = 0; ci < Ci; ci++)
                    acc += __ldg(ip + (size_t)ci * D * D * D) * wk[ci];
            }
        }
    }
    out[idx] = acc;
}

// ---------------------------------------------------------------------------
// Pair-split reduce + ReLU: two lanes per output float4 (even lane sums slabs
// [0,S/2), odd lane [S/2,S)); combined via shfl_xor(1) in fixed order, even
// lane writes. Doubles reduce thread count (profiles showed 1.7 warps/SMSP).
// Deterministic: same split and summation order every run.
// ---------------------------------------------------------------------------
__global__ void reduce_relu4p(const float4* __restrict__ part, float4* __restrict__ out,
                              int n4, int S)
{
    const int gid = blockIdx.x * blockDim.x + threadIdx.x;
    const int i = gid >> 1;
    const int half = gid & 1;
    if (i >= n4) return;
    const int Sh = S >> 1;
    const int s0 = half * Sh;

    float4 a[4];
#pragma unroll
    for (int k = 0; k < 4; k++) a[k] = make_float4(0.f, 0.f, 0.f, 0.f);
    int s = 0;
    for (; s + 4 <= Sh; s += 4) {
#pragma unroll
        for (int k = 0; k < 4; k++) {
            float4 p = part[(size_t)(s0 + s + k) * n4 + i];
            a[k].x += p.x; a[k].y += p.y; a[k].z += p.z; a[k].w += p.w;
        }
    }
    for (; s < Sh; s++) {
        float4 p = part[(size_t)(s0 + s) * n4 + i];
        a[0].x += p.x; a[0].y += p.y; a[0].z += p.z; a[0].w += p.w;
    }
    float4 v;
    v.x = (a[0].x + a[1].x) + (a[2].x + a[3].x);
    v.y = (a[0].y + a[1].y) + (a[2].y + a[3].y);
    v.z = (a[0].z + a[1].z) + (a[2].z + a[3].z);
    v.w = (a[0].w + a[1].w) + (a[2].w + a[3].w);

    float4 o;
    o.x = __shfl_xor_sync(0xffffffffu, v.x, 1);
    o.y = __shfl_xor_sync(0xffffffffu, v.y, 1);
    o.z = __shfl_xor_sync(0xffffffffu, v.z, 1);
    o.w = __shfl_xor_sync(0xffffffffu, v.w, 1);

    if (half == 0) {
        // fixed order: low-half total + high-half total
        v.x = fmaxf(v.x + o.x, 0.f);
        v.y = fmaxf(v.y + o.y, 0.f);
        v.z = fmaxf(v.z + o.z, 0.f);
        v.w = fmaxf(v.w + o.w, 0.f);
        out[i] = v;
    }
}

// ---------------------------------------------------------------------------
extern "C" void kernel_launch(void* const* d_in, const int* in_sizes, int n_in,
                              void* d_out, int out_size)
{
    (void)in_sizes; (void)n_in; (void)out_size;
    const float* x  = (const float*)d_in[0];
    const float* w1 = (const float*)d_in[1];
    const float* w2 = (const float*)d_in[2];
    const float* w3 = (const float*)d_in[3];
    const float* w4 = (const float*)d_in[4];
    const float* w5 = (const float*)d_in[5];
    const float* w6 = (const float*)d_in[6];
    float* out = (float*)d_out;

    float *h1, *h2, *h3, *h4, *h5, *p1, *p2, *p3, *p4, *p5;
    cudaGetSymbolAddress((void**)&h1, g_h1);
    cudaGetSymbolAddress((void**)&h2, g_h2);
    cudaGetSymbolAddress((void**)&h3, g_h3);
    cudaGetSymbolAddress((void**)&h4, g_h4);
    cudaGetSymbolAddress((void**)&h5, g_h5);
    cudaGetSymbolAddress((void**)&p1, g_p1);
    cudaGetSymbolAddress((void**)&p2, g_p2);
    cudaGetSymbolAddress((void**)&p3, g_p3);
    cudaGetSymbolAddress((void**)&p4, g_p4);
    cudaGetSymbolAddress((void**)&p5, g_p5);

    // L1: 1024->512, 4^3->8^3, s2. 128 co-quads, split 16 (R10 exact).
    ct_s2p<4, 2><<<dim3(64, 1, 16), 128>>>(x, w1, p1, 1024, 512, 64);
    reduce_relu4p<<<(512 * 512 / 4) * 2 / 256, 256>>>((const float4*)p1, (float4*)h1,
                                                      512 * 512 / 4, 16);

    // L2: 512->256, 8^3, s1, y-paired, split 64 single launch (R10 exact).
    ct_s1y<8, 1, 2><<<dim3(16, 1, 64), dim3(64, 2, 1)>>>(h1, w2, p2, 512, 256, 8, 0);
    reduce_relu4p<<<(256 * 512 / 4) * 2 / 256, 256>>>((const float4*)p2, (float4*)h2,
                                                      256 * 512 / 4, 64);

    // L3: 256->128, 8^3->16^3, s2. 32 co-quads, split 16 (R10 exact).
    ct_s2p<8, 2><<<dim3(256, 1, 16), 32>>>(h2, w3, p3, 256, 128, 16);
    reduce_relu4p<<<(128 * 4096 / 4) * 2 / 256, 256>>>((const float4*)p3, (float4*)h3,
                                                       128 * 4096 / 4, 16);

    // L4: 128->64, 16^3, s1, y-paired. split 32 (R10 exact).
    ct_s1y<16, 2, 4><<<dim3(32, 1, 32), dim3(16, 2, 4)>>>(h3, w4, p4, 128, 64, 4, 0);
    reduce_relu4p<<<(64 * 4096 / 4) * 2 / 256, 256>>>((const float4*)p4, (float4*)h4,
                                                      64 * 4096 / 4, 32);

    // L5: 64->32, 16^3->32^3, s2 packed f32x2. split 8 (R10 exact).
    ct_s2pz<16, 8><<<dim3(128, 1, 8), dim3(16, 8, 1)>>>(h4, w5, p5, 64, 32, 8);
    reduce_relu4p<<<(32 * 32768 / 4) * 2 / 256, 256>>>((const float4*)p5, (float4*)h5,
                                                       32 * 32768 / 4, 8);

    // L6: 32->1, 32^3, s1, no ReLU.
    ct_final<<<256, 128>>>(h5, w6, out);
}